// round 7
// baseline (speedup 1.0000x reference)
#include <cuda_runtime.h>
#include <math.h>

#define NNODES 30000
#define FIN    500
#define HID    16
#define OUTC   3
#define NEDGE  960000

// ---------------- scratch (static device arrays; no allocation) -------------
__device__ float g_h0  [NNODES * HID];   // after conv stack + max-pool
__device__ float g_lin1[NNODES * HID];   // h0 @ W1
__device__ float g_acc1[NNODES * HID];   // gcn1 aggregation
__device__ float g_lin2[NNODES * 4];     // relu(acc1) @ W2 (padded to 4)
__device__ float g_acc2[NNODES * 4];     // gcn2 aggregation (padded to 4)
__device__ int   g_deg [NNODES];
__device__ float g_dinv[NNODES];

// ---------------- f32x2 packed-FMA helpers (sm_103a FFMA2) ------------------
__device__ __forceinline__ unsigned long long fma2(unsigned long long a,
                                                   unsigned long long b,
                                                   unsigned long long c)
{
    unsigned long long d;
    asm("fma.rn.f32x2 %0, %1, %2, %3;" : "=l"(d) : "l"(a), "l"(b), "l"(c));
    return d;
}
__device__ __forceinline__ unsigned long long dup2(float x)
{
    unsigned long long d;
    asm("mov.b64 %0, {%1, %1};" : "=l"(d) : "f"(x));
    return d;
}
__device__ __forceinline__ float2 unpk(unsigned long long v)
{
    float2 r;
    asm("mov.b64 {%0, %1}, %2;" : "=f"(r.x), "=f"(r.y) : "l"(v));
    return r;
}

// ---------------- fused conv1 -> relu -> conv2 -> relu -> max ----------------
// one block per node, 512 threads.
// Phase 2 layout: tid = g*128 + pg ; g = oc-group (4 oc), pg = position group (4 pos).
__global__ __launch_bounds__(512, 2)
void conv_max_kernel(const float* __restrict__ x,
                     const float* __restrict__ w1, const float* __restrict__ b1,
                     const float* __restrict__ w2, const float* __restrict__ b2)
{
    __shared__ float xs[512];                      // x padded: xs[0]=0, xs[1..500]=x
    __shared__ float a_s[HID][512];                // conv1 out, [l+1] = a[l], borders 0
    __shared__ __align__(16) float ws2p[HID*3*16]; // transposed w2: [ic][tap][oc]
    __shared__ __align__(8)  float ws1p[8*3*2];    // conv1 w packed: [cpair][tap][2]
    __shared__ __align__(8)  float bs1[16];
    __shared__ __align__(16) float bs2[16];
    __shared__ float red[4][16];

    const int tid = threadIdx.x;
    const int n   = blockIdx.x;

    // --- phase 0: load x, stage weights, zero borders ------------------------
    {
        if (tid == 0) g_deg[n] = 0;    // degree zeroing piggybacked (used later)

        if (tid < 502)
            xs[tid] = (tid == 0 || tid == 501) ? 0.f : x[n * FIN + (tid - 1)];

        // only the border cells of a_s are read without being written
        if (tid < 32) a_s[tid >> 1][(tid & 1) ? 501 : 0] = 0.f;

        // ws2p[(ic*3 + t)*16 + oc] = w2[oc*48 + ic*3 + t]
        for (int i = tid; i < HID * 3 * HID; i += 512) {
            int ic  = i / 48;
            int rem = i - ic * 48;
            int t   = rem >> 4;
            int oc  = rem & 15;
            ws2p[i] = w2[oc * 48 + ic * 3 + t];
        }
        // conv1 weights packed over channel pairs: ws1p[(cp*3+t)*2 + (c&1)]
        if (tid < 48) {
            int c = tid / 3, t = tid - c * 3;
            ws1p[((c >> 1) * 3 + t) * 2 + (c & 1)] = w1[tid];
        } else if (tid < 64)  bs1[tid - 48] = b1[tid - 48];
        else if (tid < 80)    bs2[tid - 64] = b2[tid - 64];
    }
    __syncthreads();

    // --- phase 1: conv1 (FFMA2 over channel pairs) + relu into a_s -----------
    if (tid < FIN) {
        const unsigned long long dm = dup2(xs[tid]);
        const unsigned long long d0 = dup2(xs[tid + 1]);
        const unsigned long long dp = dup2(xs[tid + 2]);
        #pragma unroll
        for (int cp = 0; cp < 8; cp++) {
            unsigned long long acc = *reinterpret_cast<const unsigned long long*>(&bs1[2 * cp]);
            acc = fma2(*reinterpret_cast<const unsigned long long*>(&ws1p[(cp * 3 + 0) * 2]), dm, acc);
            acc = fma2(*reinterpret_cast<const unsigned long long*>(&ws1p[(cp * 3 + 1) * 2]), d0, acc);
            acc = fma2(*reinterpret_cast<const unsigned long long*>(&ws1p[(cp * 3 + 2) * 2]), dp, acc);
            const float2 u = unpk(acc);
            a_s[2 * cp + 0][tid + 1] = fmaxf(u.x, 0.f);
            a_s[2 * cp + 1][tid + 1] = fmaxf(u.y, 0.f);
        }
    }
    __syncthreads();

    // --- phase 2: conv2 (FFMA2 packed over oc-pairs) + relu + max ------------
    {
        const int g  = tid >> 7;     // oc group: channels 4g .. 4g+3
        const int pg = tid & 127;    // position group: positions 4pg .. 4pg+3
        float mx0 = -1e30f, mx1 = -1e30f, mx2 = -1e30f, mx3 = -1e30f;

        if (pg < 125) {              // p0 <= 496 -> all 4 positions valid
            const int p0 = pg << 2;
            const unsigned long long b01 = *reinterpret_cast<const unsigned long long*>(&bs2[4 * g]);
            const unsigned long long b23 = *reinterpret_cast<const unsigned long long*>(&bs2[4 * g + 2]);
            unsigned long long acc[4][2];
            #pragma unroll
            for (int r = 0; r < 4; r++) { acc[r][0] = b01; acc[r][1] = b23; }

            #pragma unroll
            for (int ic = 0; ic < HID; ic++) {
                const float4 av0 = *reinterpret_cast<const float4*>(&a_s[ic][p0]);
                const float2 av1 = *reinterpret_cast<const float2*>(&a_s[ic][p0 + 4]);
                unsigned long long d[6];
                d[0] = dup2(av0.x); d[1] = dup2(av0.y); d[2] = dup2(av0.z);
                d[3] = dup2(av0.w); d[4] = dup2(av1.x); d[5] = dup2(av1.y);

                const ulonglong2 w0  = *reinterpret_cast<const ulonglong2*>(&ws2p[(ic * 3 + 0) * 16 + 4 * g]);
                const ulonglong2 w1v = *reinterpret_cast<const ulonglong2*>(&ws2p[(ic * 3 + 1) * 16 + 4 * g]);
                const ulonglong2 w2v = *reinterpret_cast<const ulonglong2*>(&ws2p[(ic * 3 + 2) * 16 + 4 * g]);

                #pragma unroll
                for (int r = 0; r < 4; r++) {
                    acc[r][0] = fma2(w0.x,  d[r],     acc[r][0]);
                    acc[r][1] = fma2(w0.y,  d[r],     acc[r][1]);
                    acc[r][0] = fma2(w1v.x, d[r + 1], acc[r][0]);
                    acc[r][1] = fma2(w1v.y, d[r + 1], acc[r][1]);
                    acc[r][0] = fma2(w2v.x, d[r + 2], acc[r][0]);
                    acc[r][1] = fma2(w2v.y, d[r + 2], acc[r][1]);
                }
            }
            #pragma unroll
            for (int r = 0; r < 4; r++) {
                const float2 u0 = unpk(acc[r][0]);
                const float2 u1 = unpk(acc[r][1]);
                mx0 = fmaxf(mx0, u0.x); mx1 = fmaxf(mx1, u0.y);
                mx2 = fmaxf(mx2, u1.x); mx3 = fmaxf(mx3, u1.y);
            }
        }
        // warp reduce (all lanes in a warp share the same oc group)
        #pragma unroll
        for (int off = 16; off; off >>= 1) {
            mx0 = fmaxf(mx0, __shfl_xor_sync(0xffffffffu, mx0, off));
            mx1 = fmaxf(mx1, __shfl_xor_sync(0xffffffffu, mx1, off));
            mx2 = fmaxf(mx2, __shfl_xor_sync(0xffffffffu, mx2, off));
            mx3 = fmaxf(mx3, __shfl_xor_sync(0xffffffffu, mx3, off));
        }
        const int lane = tid & 31;
        const int wig  = (tid >> 5) & 3;   // warp index within oc group
        if (lane == 0) {
            red[wig][4 * g + 0] = mx0;
            red[wig][4 * g + 1] = mx1;
            red[wig][4 * g + 2] = mx2;
            red[wig][4 * g + 3] = mx3;
        }
        __syncthreads();
        if (tid < HID) {
            float m = fmaxf(fmaxf(red[0][tid], red[1][tid]),
                            fmaxf(red[2][tid], red[3][tid]));
            g_h0[n * HID + tid] = fmaxf(m, 0.f);   // relu(max) == max(relu)
        }
    }
}

// ---------------- degree count (g_deg zeroed in conv_max) --------------------
__global__ void deg_count_kernel(const int* __restrict__ dst)
{
    int i = blockIdx.x * blockDim.x + threadIdx.x;
    if (i < NEDGE) atomicAdd(&g_deg[dst[i]], 1);
}

// ---------------- gcn1: dinv + linear + self-loop init -----------------------
__global__ void lin1_kernel(const float* __restrict__ W, const float* __restrict__ b)
{
    __shared__ float Ws[HID * HID];
    __shared__ float bs[HID];
    const int tid = threadIdx.x;
    if (tid < HID * HID) Ws[tid] = W[tid];
    if (tid < HID)       bs[tid] = b[tid];
    __syncthreads();

    const int i = blockIdx.x * blockDim.x + tid;
    if (i >= NNODES) return;

    float h[HID];
    const float4* hp = reinterpret_cast<const float4*>(&g_h0[i * HID]);
    #pragma unroll
    for (int q = 0; q < 4; q++) {
        float4 v = hp[q];
        h[q * 4 + 0] = v.x; h[q * 4 + 1] = v.y; h[q * 4 + 2] = v.z; h[q * 4 + 3] = v.w;
    }
    float acc[HID];
    #pragma unroll
    for (int c = 0; c < HID; c++) acc[c] = 0.f;
    #pragma unroll
    for (int in = 0; in < HID; in++) {
        const float hv = h[in];
        #pragma unroll
        for (int c = 0; c < HID; c++) acc[c] = fmaf(hv, Ws[in * HID + c], acc[c]);
    }
    const float di = rsqrtf((float)(g_deg[i] + 1));   // +1 self loop
    g_dinv[i] = di;
    const float d2 = di * di;
    #pragma unroll
    for (int c = 0; c < HID; c++) {
        g_lin1[i * HID + c] = acc[c];
        g_acc1[i * HID + c] = fmaf(d2, acc[c], bs[c]);  // self loop + bias
    }
}

// ---------------- gcn1: edge scatter (1 thread per edge, 16 REDG) ------------
__global__ void scatter1_kernel(const int* __restrict__ src, const int* __restrict__ dst)
{
    int e = blockIdx.x * blockDim.x + threadIdx.x;
    if (e >= NEDGE) return;
    const int s = src[e];
    const int d = dst[e];
    const float w = g_dinv[s] * g_dinv[d];
    const float4* vp = reinterpret_cast<const float4*>(&g_lin1[s * HID]);
    float* out = &g_acc1[d * HID];
    #pragma unroll
    for (int q = 0; q < 4; q++) {
        const float4 v = vp[q];
        atomicAdd(out + 4 * q + 0, w * v.x);
        atomicAdd(out + 4 * q + 1, w * v.y);
        atomicAdd(out + 4 * q + 2, w * v.z);
        atomicAdd(out + 4 * q + 3, w * v.w);
    }
}

// ---------------- gcn2: relu + linear(16->3) + self-loop init ----------------
__global__ void lin2_kernel(const float* __restrict__ W, const float* __restrict__ b)
{
    __shared__ float Ws[HID * OUTC];
    __shared__ float bs[OUTC];
    const int tid = threadIdx.x;
    if (tid < HID * OUTC) Ws[tid] = W[tid];
    if (tid < OUTC)       bs[tid] = b[tid];
    __syncthreads();

    const int i = blockIdx.x * blockDim.x + tid;
    if (i >= NNODES) return;

    float h[HID];
    const float4* hp = reinterpret_cast<const float4*>(&g_acc1[i * HID]);
    #pragma unroll
    for (int q = 0; q < 4; q++) {
        float4 v = hp[q];
        h[q * 4 + 0] = fmaxf(v.x, 0.f); h[q * 4 + 1] = fmaxf(v.y, 0.f);
        h[q * 4 + 2] = fmaxf(v.z, 0.f); h[q * 4 + 3] = fmaxf(v.w, 0.f);
    }
    float acc[OUTC] = {0.f, 0.f, 0.f};
    #pragma unroll
    for (int in = 0; in < HID; in++) {
        const float hv = h[in];
        #pragma unroll
        for (int c = 0; c < OUTC; c++) acc[c] = fmaf(hv, Ws[in * OUTC + c], acc[c]);
    }
    const float di = g_dinv[i];
    const float d2 = di * di;
    #pragma unroll
    for (int c = 0; c < OUTC; c++) {
        g_lin2[i * 4 + c] = acc[c];
        g_acc2[i * 4 + c] = fmaf(d2, acc[c], bs[c]);
    }
    g_lin2[i * 4 + 3] = 0.f;
    g_acc2[i * 4 + 3] = 0.f;
}

// ---------------- gcn2: edge scatter (1 thread per edge, 3 channels) ---------
__global__ void scatter2_kernel(const int* __restrict__ src, const int* __restrict__ dst)
{
    int e = blockIdx.x * blockDim.x + threadIdx.x;
    if (e >= NEDGE) return;
    const int s = src[e];
    const int d = dst[e];
    const float w = g_dinv[s] * g_dinv[d];
    const float4 v = *reinterpret_cast<const float4*>(&g_lin2[s * 4]);
    float* out = &g_acc2[d * 4];
    atomicAdd(out + 0, w * v.x);
    atomicAdd(out + 1, w * v.y);
    atomicAdd(out + 2, w * v.z);
}

// ---------------- log_softmax ------------------------------------------------
__global__ void logsoftmax_kernel(float* __restrict__ out)
{
    int i = blockIdx.x * blockDim.x + threadIdx.x;
    if (i >= NNODES) return;
    const float z0 = g_acc2[i * 4 + 0];
    const float z1 = g_acc2[i * 4 + 1];
    const float z2 = g_acc2[i * 4 + 2];
    const float m  = fmaxf(z0, fmaxf(z1, z2));
    const float s  = expf(z0 - m) + expf(z1 - m) + expf(z2 - m);
    const float l  = m + logf(s);
    out[i * 3 + 0] = z0 - l;
    out[i * 3 + 1] = z1 - l;
    out[i * 3 + 2] = z2 - l;
}

// ---------------- launcher ---------------------------------------------------
extern "C" void kernel_launch(void* const* d_in, const int* in_sizes, int n_in,
                              void* d_out, int out_size)
{
    const float* x       = (const float*)d_in[0];
    const float* conv1_w = (const float*)d_in[1];
    const float* conv1_b = (const float*)d_in[2];
    const float* conv2_w = (const float*)d_in[3];
    const float* conv2_b = (const float*)d_in[4];
    const float* gcn1_w  = (const float*)d_in[5];
    const float* gcn1_b  = (const float*)d_in[6];
    const float* gcn2_w  = (const float*)d_in[7];
    const float* gcn2_b  = (const float*)d_in[8];
    const int*   edges   = (const int*)d_in[9];   // (2, E): row0 src, row1 dst
    const int*   src     = edges;
    const int*   dst     = edges + NEDGE;
    float*       out     = (float*)d_out;

    conv_max_kernel<<<NNODES, 512>>>(x, conv1_w, conv1_b, conv2_w, conv2_b);

    deg_count_kernel<<<(NEDGE + 255) / 256, 256>>>(dst);

    lin1_kernel    <<<(NNODES + 255) / 256, 256>>>(gcn1_w, gcn1_b);
    scatter1_kernel<<<(NEDGE + 255) / 256, 256>>>(src, dst);

    lin2_kernel    <<<(NNODES + 255) / 256, 256>>>(gcn2_w, gcn2_b);
    scatter2_kernel<<<(NEDGE + 255) / 256, 256>>>(src, dst);

    logsoftmax_kernel<<<(NNODES + 255) / 256, 256>>>(out);
}

// round 8
// speedup vs baseline: 1.1008x; 1.1008x over previous
#include <cuda_runtime.h>
#include <math.h>

#define NNODES 30000
#define FIN    500
#define HID    16
#define OUTC   3
#define NEDGE  960000

// ---------------- scratch (static device arrays; no allocation) -------------
__device__ float g_h0  [NNODES * HID];   // after conv stack + max-pool
__device__ float g_lin1[NNODES * HID];   // h0 @ W1
__device__ float g_acc1[NNODES * HID];   // gcn1 aggregation
__device__ float g_lin2[NNODES * 4];     // relu(acc1) @ W2 (padded to 4)
__device__ float g_acc2[NNODES * 4];     // gcn2 aggregation (padded to 4)
__device__ int   g_deg [NNODES];
__device__ float g_dinv[NNODES];

// ---------------- f32x2 packed-FMA helpers (sm_103a FFMA2) ------------------
__device__ __forceinline__ unsigned long long fma2(unsigned long long a,
                                                   unsigned long long b,
                                                   unsigned long long c)
{
    unsigned long long d;
    asm("fma.rn.f32x2 %0, %1, %2, %3;" : "=l"(d) : "l"(a), "l"(b), "l"(c));
    return d;
}
__device__ __forceinline__ unsigned long long dup2(float x)
{
    unsigned long long d;
    asm("mov.b64 %0, {%1, %1};" : "=l"(d) : "f"(x));
    return d;
}
__device__ __forceinline__ float2 unpk(unsigned long long v)
{
    float2 r;
    asm("mov.b64 {%0, %1}, %2;" : "=f"(r.x), "=f"(r.y) : "l"(v));
    return r;
}

// ---------------- 128-bit global float4 reduction (sm_90+) -------------------
__device__ __forceinline__ void red_add_v4(float* p, float a, float b, float c, float d)
{
    asm volatile("red.global.add.v4.f32 [%0], {%1, %2, %3, %4};"
                 :: "l"(p), "f"(a), "f"(b), "f"(c), "f"(d) : "memory");
}

// ---------------- fused conv1 -> relu -> conv2 -> relu -> max ----------------
// one block per node, 512 threads.
// Phase 2 layout: tid = g*128 + pg ; g = oc-group (4 oc), pg = position group (4 pos).
__global__ __launch_bounds__(512, 2)
void conv_max_kernel(const float* __restrict__ x,
                     const float* __restrict__ w1, const float* __restrict__ b1,
                     const float* __restrict__ w2, const float* __restrict__ b2)
{
    __shared__ float xs[512];                      // x padded: xs[0]=0, xs[1..500]=x
    __shared__ float a_s[HID][512];                // conv1 out, [l+1] = a[l], borders 0
    __shared__ __align__(16) float ws2p[HID*3*16]; // transposed w2: [ic][tap][oc]
    __shared__ __align__(8)  float ws1p[8*3*2];    // conv1 w packed: [cpair][tap][2]
    __shared__ __align__(8)  float bs1[16];
    __shared__ __align__(16) float bs2[16];
    __shared__ float red[4][16];

    const int tid = threadIdx.x;
    const int n   = blockIdx.x;

    // --- phase 0: load x, stage weights, zero borders ------------------------
    {
        if (tid == 0) g_deg[n] = 0;    // degree zeroing piggybacked (used later)

        if (tid < 502)
            xs[tid] = (tid == 0 || tid == 501) ? 0.f : x[n * FIN + (tid - 1)];

        // only the border cells of a_s are read without being written
        if (tid < 32) a_s[tid >> 1][(tid & 1) ? 501 : 0] = 0.f;

        // ws2p[(ic*3 + t)*16 + oc] = w2[oc*48 + ic*3 + t]
        for (int i = tid; i < HID * 3 * HID; i += 512) {
            int ic  = i / 48;
            int rem = i - ic * 48;
            int t   = rem >> 4;
            int oc  = rem & 15;
            ws2p[i] = w2[oc * 48 + ic * 3 + t];
        }
        // conv1 weights packed over channel pairs: ws1p[(cp*3+t)*2 + (c&1)]
        if (tid < 48) {
            int c = tid / 3, t = tid - c * 3;
            ws1p[((c >> 1) * 3 + t) * 2 + (c & 1)] = w1[tid];
        } else if (tid < 64)  bs1[tid - 48] = b1[tid - 48];
        else if (tid < 80)    bs2[tid - 64] = b2[tid - 64];
    }
    __syncthreads();

    // --- phase 1: conv1 (FFMA2 over channel pairs) + relu into a_s -----------
    if (tid < FIN) {
        const unsigned long long dm = dup2(xs[tid]);
        const unsigned long long d0 = dup2(xs[tid + 1]);
        const unsigned long long dp = dup2(xs[tid + 2]);
        #pragma unroll
        for (int cp = 0; cp < 8; cp++) {
            unsigned long long acc = *reinterpret_cast<const unsigned long long*>(&bs1[2 * cp]);
            acc = fma2(*reinterpret_cast<const unsigned long long*>(&ws1p[(cp * 3 + 0) * 2]), dm, acc);
            acc = fma2(*reinterpret_cast<const unsigned long long*>(&ws1p[(cp * 3 + 1) * 2]), d0, acc);
            acc = fma2(*reinterpret_cast<const unsigned long long*>(&ws1p[(cp * 3 + 2) * 2]), dp, acc);
            const float2 u = unpk(acc);
            a_s[2 * cp + 0][tid + 1] = fmaxf(u.x, 0.f);
            a_s[2 * cp + 1][tid + 1] = fmaxf(u.y, 0.f);
        }
    }
    __syncthreads();

    // --- phase 2: conv2 (FFMA2 packed over oc-pairs) + relu + max ------------
    {
        const int g  = tid >> 7;     // oc group: channels 4g .. 4g+3
        const int pg = tid & 127;    // position group: positions 4pg .. 4pg+3
        float mx0 = -1e30f, mx1 = -1e30f, mx2 = -1e30f, mx3 = -1e30f;

        if (pg < 125) {              // p0 <= 496 -> all 4 positions valid
            const int p0 = pg << 2;
            const unsigned long long b01 = *reinterpret_cast<const unsigned long long*>(&bs2[4 * g]);
            const unsigned long long b23 = *reinterpret_cast<const unsigned long long*>(&bs2[4 * g + 2]);
            unsigned long long acc[4][2];
            #pragma unroll
            for (int r = 0; r < 4; r++) { acc[r][0] = b01; acc[r][1] = b23; }

            #pragma unroll
            for (int ic = 0; ic < HID; ic++) {
                const float4 av0 = *reinterpret_cast<const float4*>(&a_s[ic][p0]);
                const float2 av1 = *reinterpret_cast<const float2*>(&a_s[ic][p0 + 4]);
                unsigned long long d[6];
                d[0] = dup2(av0.x); d[1] = dup2(av0.y); d[2] = dup2(av0.z);
                d[3] = dup2(av0.w); d[4] = dup2(av1.x); d[5] = dup2(av1.y);

                const ulonglong2 w0  = *reinterpret_cast<const ulonglong2*>(&ws2p[(ic * 3 + 0) * 16 + 4 * g]);
                const ulonglong2 w1v = *reinterpret_cast<const ulonglong2*>(&ws2p[(ic * 3 + 1) * 16 + 4 * g]);
                const ulonglong2 w2v = *reinterpret_cast<const ulonglong2*>(&ws2p[(ic * 3 + 2) * 16 + 4 * g]);

                #pragma unroll
                for (int r = 0; r < 4; r++) {
                    acc[r][0] = fma2(w0.x,  d[r],     acc[r][0]);
                    acc[r][1] = fma2(w0.y,  d[r],     acc[r][1]);
                    acc[r][0] = fma2(w1v.x, d[r + 1], acc[r][0]);
                    acc[r][1] = fma2(w1v.y, d[r + 1], acc[r][1]);
                    acc[r][0] = fma2(w2v.x, d[r + 2], acc[r][0]);
                    acc[r][1] = fma2(w2v.y, d[r + 2], acc[r][1]);
                }
            }
            #pragma unroll
            for (int r = 0; r < 4; r++) {
                const float2 u0 = unpk(acc[r][0]);
                const float2 u1 = unpk(acc[r][1]);
                mx0 = fmaxf(mx0, u0.x); mx1 = fmaxf(mx1, u0.y);
                mx2 = fmaxf(mx2, u1.x); mx3 = fmaxf(mx3, u1.y);
            }
        }
        // warp reduce (all lanes in a warp share the same oc group)
        #pragma unroll
        for (int off = 16; off; off >>= 1) {
            mx0 = fmaxf(mx0, __shfl_xor_sync(0xffffffffu, mx0, off));
            mx1 = fmaxf(mx1, __shfl_xor_sync(0xffffffffu, mx1, off));
            mx2 = fmaxf(mx2, __shfl_xor_sync(0xffffffffu, mx2, off));
            mx3 = fmaxf(mx3, __shfl_xor_sync(0xffffffffu, mx3, off));
        }
        const int lane = tid & 31;
        const int wig  = (tid >> 5) & 3;   // warp index within oc group
        if (lane == 0) {
            red[wig][4 * g + 0] = mx0;
            red[wig][4 * g + 1] = mx1;
            red[wig][4 * g + 2] = mx2;
            red[wig][4 * g + 3] = mx3;
        }
        __syncthreads();
        if (tid < HID) {
            float m = fmaxf(fmaxf(red[0][tid], red[1][tid]),
                            fmaxf(red[2][tid], red[3][tid]));
            g_h0[n * HID + tid] = fmaxf(m, 0.f);   // relu(max) == max(relu)
        }
    }
}

// ---------------- degree count (g_deg zeroed in conv_max) --------------------
__global__ void deg_count_kernel(const int* __restrict__ dst)
{
    int i = blockIdx.x * blockDim.x + threadIdx.x;
    if (i < NEDGE) atomicAdd(&g_deg[dst[i]], 1);
}

// ---------------- gcn1: dinv + linear + self-loop init -----------------------
__global__ void lin1_kernel(const float* __restrict__ W, const float* __restrict__ b)
{
    __shared__ float Ws[HID * HID];
    __shared__ float bs[HID];
    const int tid = threadIdx.x;
    if (tid < HID * HID) Ws[tid] = W[tid];
    if (tid < HID)       bs[tid] = b[tid];
    __syncthreads();

    const int i = blockIdx.x * blockDim.x + tid;
    if (i >= NNODES) return;

    float h[HID];
    const float4* hp = reinterpret_cast<const float4*>(&g_h0[i * HID]);
    #pragma unroll
    for (int q = 0; q < 4; q++) {
        float4 v = hp[q];
        h[q * 4 + 0] = v.x; h[q * 4 + 1] = v.y; h[q * 4 + 2] = v.z; h[q * 4 + 3] = v.w;
    }
    float acc[HID];
    #pragma unroll
    for (int c = 0; c < HID; c++) acc[c] = 0.f;
    #pragma unroll
    for (int in = 0; in < HID; in++) {
        const float hv = h[in];
        #pragma unroll
        for (int c = 0; c < HID; c++) acc[c] = fmaf(hv, Ws[in * HID + c], acc[c]);
    }
    const float di = rsqrtf((float)(g_deg[i] + 1));   // +1 self loop
    g_dinv[i] = di;
    const float d2 = di * di;
    #pragma unroll
    for (int c = 0; c < HID; c++) {
        g_lin1[i * HID + c] = acc[c];
        g_acc1[i * HID + c] = fmaf(d2, acc[c], bs[c]);  // self loop + bias
    }
}

// ---------------- gcn1: edge scatter (1 thread/edge, 4x red.v4.f32) ----------
__global__ void scatter1_kernel(const int* __restrict__ src, const int* __restrict__ dst)
{
    int e = blockIdx.x * blockDim.x + threadIdx.x;
    if (e >= NEDGE) return;
    const int s = src[e];
    const int d = dst[e];
    const float w = g_dinv[s] * g_dinv[d];
    const float4* vp = reinterpret_cast<const float4*>(&g_lin1[s * HID]);
    float* out = &g_acc1[d * HID];
    #pragma unroll
    for (int q = 0; q < 4; q++) {
        const float4 v = vp[q];
        red_add_v4(out + 4 * q, w * v.x, w * v.y, w * v.z, w * v.w);
    }
}

// ---------------- gcn2: relu + linear(16->3) + self-loop init ----------------
__global__ void lin2_kernel(const float* __restrict__ W, const float* __restrict__ b)
{
    __shared__ float Ws[HID * OUTC];
    __shared__ float bs[OUTC];
    const int tid = threadIdx.x;
    if (tid < HID * OUTC) Ws[tid] = W[tid];
    if (tid < OUTC)       bs[tid] = b[tid];
    __syncthreads();

    const int i = blockIdx.x * blockDim.x + tid;
    if (i >= NNODES) return;

    float h[HID];
    const float4* hp = reinterpret_cast<const float4*>(&g_acc1[i * HID]);
    #pragma unroll
    for (int q = 0; q < 4; q++) {
        float4 v = hp[q];
        h[q * 4 + 0] = fmaxf(v.x, 0.f); h[q * 4 + 1] = fmaxf(v.y, 0.f);
        h[q * 4 + 2] = fmaxf(v.z, 0.f); h[q * 4 + 3] = fmaxf(v.w, 0.f);
    }
    float acc[OUTC] = {0.f, 0.f, 0.f};
    #pragma unroll
    for (int in = 0; in < HID; in++) {
        const float hv = h[in];
        #pragma unroll
        for (int c = 0; c < OUTC; c++) acc[c] = fmaf(hv, Ws[in * OUTC + c], acc[c]);
    }
    const float di = g_dinv[i];
    const float d2 = di * di;
    #pragma unroll
    for (int c = 0; c < OUTC; c++) {
        g_lin2[i * 4 + c] = acc[c];
        g_acc2[i * 4 + c] = fmaf(d2, acc[c], bs[c]);
    }
    g_lin2[i * 4 + 3] = 0.f;
    g_acc2[i * 4 + 3] = 0.f;   // lane 3 is a zero pad; red.v4 adds 0 to it
}

// ---------------- gcn2: edge scatter (1 thread/edge, 1x red.v4.f32) ----------
__global__ void scatter2_kernel(const int* __restrict__ src, const int* __restrict__ dst)
{
    int e = blockIdx.x * blockDim.x + threadIdx.x;
    if (e >= NEDGE) return;
    const int s = src[e];
    const int d = dst[e];
    const float w = g_dinv[s] * g_dinv[d];
    const float4 v = *reinterpret_cast<const float4*>(&g_lin2[s * 4]);
    red_add_v4(&g_acc2[d * 4], w * v.x, w * v.y, w * v.z, 0.f);
}

// ---------------- log_softmax ------------------------------------------------
__global__ void logsoftmax_kernel(float* __restrict__ out)
{
    int i = blockIdx.x * blockDim.x + threadIdx.x;
    if (i >= NNODES) return;
    const float z0 = g_acc2[i * 4 + 0];
    const float z1 = g_acc2[i * 4 + 1];
    const float z2 = g_acc2[i * 4 + 2];
    const float m  = fmaxf(z0, fmaxf(z1, z2));
    const float s  = expf(z0 - m) + expf(z1 - m) + expf(z2 - m);
    const float l  = m + logf(s);
    out[i * 3 + 0] = z0 - l;
    out[i * 3 + 1] = z1 - l;
    out[i * 3 + 2] = z2 - l;
}

// ---------------- launcher ---------------------------------------------------
extern "C" void kernel_launch(void* const* d_in, const int* in_sizes, int n_in,
                              void* d_out, int out_size)
{
    const float* x       = (const float*)d_in[0];
    const float* conv1_w = (const float*)d_in[1];
    const float* conv1_b = (const float*)d_in[2];
    const float* conv2_w = (const float*)d_in[3];
    const float* conv2_b = (const float*)d_in[4];
    const float* gcn1_w  = (const float*)d_in[5];
    const float* gcn1_b  = (const float*)d_in[6];
    const float* gcn2_w  = (const float*)d_in[7];
    const float* gcn2_b  = (const float*)d_in[8];
    const int*   edges   = (const int*)d_in[9];   // (2, E): row0 src, row1 dst
    const int*   src     = edges;
    const int*   dst     = edges + NEDGE;
    float*       out     = (float*)d_out;

    conv_max_kernel<<<NNODES, 512>>>(x, conv1_w, conv1_b, conv2_w, conv2_b);

    deg_count_kernel<<<(NEDGE + 255) / 256, 256>>>(dst);

    lin1_kernel    <<<(NNODES + 255) / 256, 256>>>(gcn1_w, gcn1_b);
    scatter1_kernel<<<(NEDGE + 255) / 256, 256>>>(src, dst);

    lin2_kernel    <<<(NNODES + 255) / 256, 256>>>(gcn2_w, gcn2_b);
    scatter2_kernel<<<(NEDGE + 255) / 256, 256>>>(src, dst);

    logsoftmax_kernel<<<(NNODES + 255) / 256, 256>>>(out);
}